// round 9
// baseline (speedup 1.0000x reference)
#include <cuda_runtime.h>
#include <mma.h>
#include <cstdint>

using namespace nvcuda;

#define T_STEPS 1024
#define B_SZ    64
#define H_SZ    1024
#define BH      (B_SZ * H_SZ)          /* 65536 */
#define TBH     (T_STEPS * BH)

// ---------------- scan config ----------------
#define RSZ   16         // batch rows per block
#define CSZ   32         // output cols per block
#define NBLK  128        // 4 row-groups x 32 col-blocks
#define KCH   64         // k columns per warp chunk
#define NWARP 16
#define SST   36         // stage row stride (floats)
#define FPAD  32         // one flag per 128B L2 line
#define NFLG  (NBLK * NWARP)
#define XQ    4          // xp prefetch queue depth

__device__ unsigned g_wflags[NFLG * FPAD];       // per-warp progress flags
__device__ __align__(16) float g_hswz[2][BH];    // fragment-major h ping-pong

// ---------------- asm helpers ----------------
__device__ __forceinline__ unsigned ldacq(const unsigned* p) {
    unsigned v;
    asm volatile("ld.acquire.gpu.global.u32 %0, [%1];" : "=r"(v) : "l"(p));
    return v;
}
__device__ __forceinline__ unsigned ldflag(const unsigned* p) {
    unsigned v;
    asm volatile("ld.global.cg.u32 %0, [%1];" : "=r"(v) : "l"(p));
    return v;
}
__device__ __forceinline__ void strel(unsigned* p, unsigned v) {
    asm volatile("st.release.gpu.global.u32 [%0], %1;" :: "l"(p), "r"(v) : "memory");
}
__device__ __forceinline__ float ldcs(const float* p) {
    float v;
    asm volatile("ld.global.cs.f32 %0, [%1];" : "=f"(v) : "l"(p));
    return v;
}
__device__ __forceinline__ void stcs(float* p, float v) {
    asm volatile("st.global.cs.f32 [%0], %1;" :: "l"(p), "f"(v));
}
__device__ __forceinline__ void mma_tf32(float acc[4], const uint4& a, const unsigned b[2]) {
    asm volatile("mma.sync.aligned.m16n8k8.row.col.f32.tf32.tf32.f32 "
                 "{%0,%1,%2,%3}, {%4,%5,%6,%7}, {%8,%9}, {%0,%1,%2,%3};"
                 : "+f"(acc[0]), "+f"(acc[1]), "+f"(acc[2]), "+f"(acc[3])
                 : "r"(a.x), "r"(a.y), "r"(a.z), "r"(a.w), "r"(b[0]), "r"(b[1]));
}

// ---------------------------------------------------------------------------
// Kernel A: xproj = xs @ Wih — register double-buffered (round-6 best config)
// ---------------------------------------------------------------------------
__global__ void __launch_bounds__(256) xproj_gemm(const float* __restrict__ xs,
                                                  const float* __restrict__ Wih,
                                                  float* __restrict__ C) {
    __shared__ float As[128 * 36];
    __shared__ float Bs[32 * 136];

    const int tid = threadIdx.x;
    const int m0  = blockIdx.y * 128;
    const int n0  = blockIdx.x * 128;
    const int w   = tid >> 5;
    const int wm  = w >> 1;
    const int wn  = w & 1;

    wmma::fragment<wmma::accumulator, 16, 16, 8, float> cf[2][4];
#pragma unroll
    for (int i = 0; i < 2; i++)
#pragma unroll
        for (int j = 0; j < 4; j++) wmma::fill_fragment(cf[i][j], 0.0f);

    float4 a4[4], b4[4];
#pragma unroll
    for (int i = 0; i < 4; i++) {
        int idx = tid + i * 256;
        int r = idx >> 3, q = (idx & 7) * 4;
        a4[i] = *reinterpret_cast<const float4*>(xs + (size_t)(m0 + r) * H_SZ + q);
    }
#pragma unroll
    for (int i = 0; i < 4; i++) {
        int idx = tid + i * 256;
        int r = idx >> 5, q = (idx & 31) * 4;
        b4[i] = *reinterpret_cast<const float4*>(Wih + (size_t)r * H_SZ + n0 + q);
    }

    for (int kt = 0; kt < H_SZ; kt += 32) {
#pragma unroll
        for (int i = 0; i < 4; i++) {
            int idx = tid + i * 256;
            int r = idx >> 3, q = (idx & 7) * 4;
            float4 o;
            o.x = wmma::__float_to_tf32(a4[i].x);
            o.y = wmma::__float_to_tf32(a4[i].y);
            o.z = wmma::__float_to_tf32(a4[i].z);
            o.w = wmma::__float_to_tf32(a4[i].w);
            *reinterpret_cast<float4*>(As + r * 36 + q) = o;
        }
#pragma unroll
        for (int i = 0; i < 4; i++) {
            int idx = tid + i * 256;
            int r = idx >> 5, q = (idx & 31) * 4;
            float4 o;
            o.x = wmma::__float_to_tf32(b4[i].x);
            o.y = wmma::__float_to_tf32(b4[i].y);
            o.z = wmma::__float_to_tf32(b4[i].z);
            o.w = wmma::__float_to_tf32(b4[i].w);
            *reinterpret_cast<float4*>(Bs + r * 136 + q) = o;
        }
        __syncthreads();

        if (kt + 32 < H_SZ) {
#pragma unroll
            for (int i = 0; i < 4; i++) {
                int idx = tid + i * 256;
                int r = idx >> 3, q = (idx & 7) * 4;
                a4[i] = *reinterpret_cast<const float4*>(
                    xs + (size_t)(m0 + r) * H_SZ + kt + 32 + q);
            }
#pragma unroll
            for (int i = 0; i < 4; i++) {
                int idx = tid + i * 256;
                int r = idx >> 5, q = (idx & 31) * 4;
                b4[i] = *reinterpret_cast<const float4*>(
                    Wih + (size_t)(kt + 32 + r) * H_SZ + n0 + q);
            }
        }

#pragma unroll
        for (int kk = 0; kk < 4; kk++) {
            wmma::fragment<wmma::matrix_a, 16, 16, 8, wmma::precision::tf32, wmma::row_major> af[2];
            wmma::fragment<wmma::matrix_b, 16, 16, 8, wmma::precision::tf32, wmma::row_major> bf[4];
            wmma::load_matrix_sync(af[0], As + (wm * 32 + 0)  * 36 + kk * 8, 36);
            wmma::load_matrix_sync(af[1], As + (wm * 32 + 16) * 36 + kk * 8, 36);
#pragma unroll
            for (int j = 0; j < 4; j++)
                wmma::load_matrix_sync(bf[j], Bs + (kk * 8) * 136 + wn * 64 + j * 16, 136);
#pragma unroll
            for (int i = 0; i < 2; i++)
#pragma unroll
                for (int j = 0; j < 4; j++)
                    wmma::mma_sync(cf[i][j], af[i], bf[j], cf[i][j]);
        }
        __syncthreads();
    }

#pragma unroll
    for (int i = 0; i < 2; i++)
#pragma unroll
        for (int j = 0; j < 4; j++)
            wmma::store_matrix_sync(
                C + (size_t)(m0 + wm * 32 + i * 16) * H_SZ + n0 + wn * 64 + j * 16,
                cf[i][j], H_SZ, wmma::mem_row_major);
}

// ---------------------------------------------------------------------------
// Swizzle init -> g_hswz[1]  (slot (t+1)&1 is read at step t)
// ---------------------------------------------------------------------------
__global__ void swizzle_init(const float* __restrict__ init) {
    int idx = blockIdx.x * 256 + threadIdx.x;        // 0..65535
    int r = idx >> 10, gcol = idx & 1023;
    int rb = r >> 4, r16 = r & 15;
    int c = gcol >> 6, kk = (gcol >> 3) & 7, tcol = gcol & 7;
    int reg  = ((r16 >= 8) ? 1 : 0) | ((tcol >= 4) ? 2 : 0);
    int lane = 4 * (r16 & 7) + (tcol & 3);
    g_hswz[1][rb * 16384 + ((c * 8 + kk) * 32 + lane) * 4 + reg] =
        wmma::__float_to_tf32(init[idx]);
}

// ---------------------------------------------------------------------------
// Kernel B: persistent scan — warp flags, 4-step xp prefetch queue, .cs
// streaming for outs, L2-resident h exchange via g_hswz only.
// ---------------------------------------------------------------------------
__global__ void __launch_bounds__(512) rnn_scan(const float* __restrict__ Whh,
                                                const float* __restrict__ bih,
                                                const float* __restrict__ bhh,
                                                float* __restrict__ outs,
                                                float* __restrict__ carry) {
    extern __shared__ float stage[];                 // [2][NWARP*RSZ*SST]

    const int tid = threadIdx.x, bid = blockIdx.x;
    const int rb = bid & 3, jb = bid >> 2;
    const int r0 = rb * RSZ, j0 = jb * CSZ;
    const int w = tid >> 5, lane = tid & 31;
    const int g = lane >> 2, tg = lane & 3;
    const int c = (w + jb) & 15;                     // staggered chunk
    const int er = w, ec = lane;                     // this thread's h element

    unsigned* myflag = &g_wflags[(bid * NWARP + w) * FPAD];
    const unsigned base = ldflag(myflag);
    const float bsum = bih[j0 + ec] + bhh[j0 + ec];

    // swizzle slot for produced h element (er, j0+ec)
    const int pgc = j0 + ec;
    const int preg  = ((er >= 8) ? 1 : 0) | (((pgc & 7) >= 4) ? 2 : 0);
    const int plane = 4 * (er & 7) + (pgc & 3);
    const int swz_off = rb * 16384 +
        (((pgc >> 6) * 8 + ((pgc >> 3) & 7)) * 32 + plane) * 4 + preg;

    // producer-warp flag for this lane: block (rb, 2c+(lane>>4)), warp lane&15
    const unsigned* pflag =
        &g_wflags[((((unsigned)(2 * c + (lane >> 4)) << 2) | (unsigned)rb) * NWARP
                   + (lane & 15)) * FPAD];

    // Whh fragments: 8 ksteps x 4 ntiles x 2 regs = 64 registers, persistent
    unsigned Bf[8][4][2];
#pragma unroll
    for (int kk = 0; kk < 8; kk++)
#pragma unroll
        for (int nt = 0; nt < 4; nt++) {
            int krow = c * KCH + kk * 8 + tg;
            int ncol = j0 + nt * 8 + g;
            Bf[kk][nt][0] = __float_as_uint(
                wmma::__float_to_tf32(Whh[(size_t)krow * H_SZ + ncol]));
            Bf[kk][nt][1] = __float_as_uint(
                wmma::__float_to_tf32(Whh[(size_t)(krow + 4) * H_SZ + ncol]));
        }

    const size_t eoff = (size_t)(r0 + er) * H_SZ + j0 + ec;   // element offset in a BH slab

    // xp prefetch queue: xq[i] holds xproj[t] for t ≡ i (mod XQ), depth-4 ahead
    float xq[XQ];
#pragma unroll
    for (int i = 0; i < XQ; i++) xq[i] = ldcs(outs + (size_t)i * BH + eoff);

#pragma unroll 1
    for (int t = 0; t < T_STEPS; t++) {
        const float xp = xq[t & (XQ - 1)];
        if (t + XQ < T_STEPS)
            xq[t & (XQ - 1)] = ldcs(outs + (size_t)(t + XQ) * BH + eoff);

        if (t > 0) {
            for (;;) {
                int ok = (int)(ldacq(pflag) - base) >= t;
                if (__all_sync(0xffffffffu, ok)) break;
                __nanosleep(16);
            }
        }

        // A fragments: 8 coalesced LDG.128 from swizzled h_{t-1} (L2-resident)
        const uint4* ap = reinterpret_cast<const uint4*>(
            g_hswz[(t + 1) & 1] + rb * 16384 + (c * 8) * 128) + lane;

        float acc[4][4] = {{0,0,0,0},{0,0,0,0},{0,0,0,0},{0,0,0,0}};
        uint4 av = __ldcg(ap);
#pragma unroll
        for (int kk = 0; kk < 8; kk++) {
            uint4 nx;
            if (kk < 7) nx = __ldcg(ap + (kk + 1) * 32);
#pragma unroll
            for (int nt = 0; nt < 4; nt++)
                mma_tf32(acc[nt], av, Bf[kk][nt]);
            av = nx;
        }

        // stage partials into parity buffer
        float* sb = stage + (t & 1) * (NWARP * RSZ * SST);
        float* stg = sb + w * (RSZ * SST);
#pragma unroll
        for (int nt = 0; nt < 4; nt++) {
            *reinterpret_cast<float2*>(stg + g * SST + nt * 8 + 2 * tg) =
                make_float2(acc[nt][0], acc[nt][1]);
            *reinterpret_cast<float2*>(stg + (g + 8) * SST + nt * 8 + 2 * tg) =
                make_float2(acc[nt][2], acc[nt][3]);
        }
        __syncthreads();                             // the ONLY block barrier

        // epilogue: reduce 16 partials, tanh
        float v = xp + bsum;
#pragma unroll
        for (int k = 0; k < NWARP; k++)
            v += sb[k * (RSZ * SST) + er * SST + ec];
        v = wmma::__float_to_tf32(tanhf(v));

        // publish swizzled h (L2) FIRST, release own flag, then stream to DRAM
        __stcg(&g_hswz[t & 1][swz_off], v);
        __syncwarp();
        if (lane == 0) strel(myflag, base + (unsigned)(t + 1));

        stcs(outs + (size_t)t * BH + eoff, v);
        if (carry != nullptr && t == T_STEPS - 1)
            stcs(carry + eoff, v);
    }
}

// ---------------------------------------------------------------------------
extern "C" void kernel_launch(void* const* d_in, const int* in_sizes, int n_in,
                              void* d_out, int out_size) {
    const float* init = (const float*)d_in[0];
    const float* xs   = (const float*)d_in[1];
    const float* Wih  = (const float*)d_in[2];
    const float* bih  = (const float*)d_in[3];
    const float* Whh  = (const float*)d_in[4];
    const float* bhh  = (const float*)d_in[5];

    float* out   = (float*)d_out;
    float* carry = nullptr;
    float* outs;
    if (out_size == BH + TBH) { carry = out; outs = out + BH; }
    else                      { outs = out; }

    swizzle_init<<<BH / 256, 256>>>(init);
    xproj_gemm<<<dim3(H_SZ / 128, (T_STEPS * B_SZ) / 128), 256>>>(xs, Wih, outs);

    int ssmem = 2 * NWARP * RSZ * SST * (int)sizeof(float);           // 73728B
    cudaFuncSetAttribute(rnn_scan, cudaFuncAttributeMaxDynamicSharedMemorySize, ssmem);
    rnn_scan<<<NBLK, 512, ssmem>>>(Whh, bih, bhh, outs, carry);
}

// round 10
// speedup vs baseline: 1.4092x; 1.4092x over previous
#include <cuda_runtime.h>
#include <mma.h>
#include <cstdint>

using namespace nvcuda;

#define T_STEPS 1024
#define B_SZ    64
#define H_SZ    1024
#define BH      (B_SZ * H_SZ)          /* 65536 */
#define TBH     (T_STEPS * BH)

// ---------------- config ----------------
#define RSZ   16         // batch rows per block
#define CSZ   32         // output cols per block
#define NBLK  128        // 4 row-groups x 32 col-blocks
#define KCH   64         // k columns per warp chunk
#define NWARP 16
#define SST   36         // stage row stride (floats)
#define WST   36         // Wih smem row stride
#define FPAD  32         // one flag per 128B L2 line
#define RING  4          // xs-swizzle ring depth (slab t in slot t&3)

__device__ unsigned g_flags[NBLK * FPAD];
__device__ __align__(16) float g_hswz[2][BH];        // fragment-major h ping-pong
__device__ __align__(16) float g_xswz[RING][BH];     // fragment-major xs ring (1MB)

// ---------------- asm helpers ----------------
__device__ __forceinline__ unsigned ldacq(const unsigned* p) {
    unsigned v;
    asm volatile("ld.acquire.gpu.global.u32 %0, [%1];" : "=r"(v) : "l"(p));
    return v;
}
__device__ __forceinline__ unsigned ldflag(const unsigned* p) {
    unsigned v;
    asm volatile("ld.global.cg.u32 %0, [%1];" : "=r"(v) : "l"(p));
    return v;
}
__device__ __forceinline__ void relexch(unsigned* p, unsigned v) {
    unsigned old;
    asm volatile("atom.release.gpu.global.exch.b32 %0, [%1], %2;"
                 : "=r"(old) : "l"(p), "r"(v) : "memory");
}
__device__ __forceinline__ void mma_tf32(float acc[4], const uint4& a, const unsigned b[2]) {
    asm volatile("mma.sync.aligned.m16n8k8.row.col.f32.tf32.tf32.f32 "
                 "{%0,%1,%2,%3}, {%4,%5,%6,%7}, {%8,%9}, {%0,%1,%2,%3};"
                 : "+f"(acc[0]), "+f"(acc[1]), "+f"(acc[2]), "+f"(acc[3])
                 : "r"(a.x), "r"(a.y), "r"(a.z), "r"(a.w), "r"(b[0]), "r"(b[1]));
}

// fragment-major offset (within one rb slice) for element (r16, gc)
__device__ __forceinline__ int swz_rel(int r16, int gc) {
    int reg  = ((r16 >= 8) ? 1 : 0) | ((gc & 4) ? 2 : 0);
    int lane = 4 * (r16 & 7) + (gc & 3);
    return (((gc >> 6) * 8 + ((gc >> 3) & 7)) * 32 + lane) * 4 + reg;
}

// ---------------------------------------------------------------------------
// Fused persistent kernel: xproj GEMM + RNN scan in one.
// Block (rb, jb): 16 batch rows x 32 output cols. Warp w: k-chunk c=(w+jb)&15.
// Per step t: [xs[t] x Wih] MMAs (ring, guard flag>=t-1) + swizzle duty for
// xs[t+2] + [h[t-1] x Whh] MMAs (guard flag>=t) into ONE accumulator set,
// smem reduce, tanh, dual store, block flag release.
// ---------------------------------------------------------------------------
__global__ void __launch_bounds__(512) rnn_fused(const float* __restrict__ init,
                                                 const float* __restrict__ xs,
                                                 const float* __restrict__ Wih,
                                                 const float* __restrict__ bih,
                                                 const float* __restrict__ Whh,
                                                 const float* __restrict__ bhh,
                                                 float* __restrict__ outs,
                                                 float* __restrict__ carry) {
    extern __shared__ float sm[];
    float* WihS  = sm;                       // 1024*36 = 36864 f (147456 B)
    float* stage = sm + H_SZ * WST;          // 16*16*36 = 9216 f (36864 B)

    const int tid = threadIdx.x, bid = blockIdx.x;
    const int rb = bid & 3, jb = bid >> 2;
    const int r0 = rb * RSZ, j0 = jb * CSZ;
    const int w = tid >> 5, lane = tid & 31;
    const int g = lane >> 2, tg = lane & 3;
    const int c = (w + jb) & 15;             // staggered chunk
    const int er = w, ec = lane;             // this thread's output element

    unsigned* myflag = &g_flags[bid * FPAD];
    const unsigned base = ldflag(myflag);
    const float bsum = bih[j0 + ec] + bhh[j0 + ec];

    // fragment slot (within rb slice) of this thread's (er, j0+ec) element —
    // used for BOTH the h publish and the xs swizzle duty (same coordinates).
    const int myswz = swz_rel(er, j0 + ec);
    const int rbbase = rb * 16384;

    // producer flags for chunk c: blocks (rb, 2c) and (rb, 2c+1)
    const unsigned* pflag =
        &g_flags[((((unsigned)(2 * c + (lane & 1))) << 2) | (unsigned)rb) * FPAD];

    // ---- prologue: Wih slice -> smem (tf32) ----
#pragma unroll
    for (int i = 0; i < 64; i++) {
        int idx = tid + i * 512;             // 0..32767
        int k = idx >> 5, n = idx & 31;
        WihS[k * WST + n] = wmma::__float_to_tf32(Wih[(size_t)k * H_SZ + j0 + n]);
    }

    // ---- prologue: Whh fragments -> registers (64 regs) ----
    unsigned Bf[8][4][2];
#pragma unroll
    for (int kk = 0; kk < 8; kk++)
#pragma unroll
        for (int nt = 0; nt < 4; nt++) {
            int krow = c * KCH + kk * 8 + tg;
            int ncol = j0 + nt * 8 + g;
            Bf[kk][nt][0] = __float_as_uint(
                wmma::__float_to_tf32(Whh[(size_t)krow * H_SZ + ncol]));
            Bf[kk][nt][1] = __float_as_uint(
                wmma::__float_to_tf32(Whh[(size_t)(krow + 4) * H_SZ + ncol]));
        }

    // ---- prologue: duplicate-swizzle init -> hswz[1], xs[0]->ring0, xs[1]->ring1
    // (every same-rb block writes identical values: benign, no cross-block sync)
#pragma unroll 4
    for (int i = 0; i < 32; i++) {
        int idx = tid + i * 512;             // 0..16383
        int r16 = idx >> 10, gc = idx & 1023;
        int off = rbbase + swz_rel(r16, gc);
        size_t src = (size_t)(r0 + r16) * H_SZ + gc;
        g_hswz[1][off]  = wmma::__float_to_tf32(init[src]);
        g_xswz[0][off]  = wmma::__float_to_tf32(__ldcg(xs + src));
        g_xswz[1][off]  = wmma::__float_to_tf32(__ldcg(xs + BH + src));
    }
    __syncthreads();

#pragma unroll 1
    for (int t = 0; t < T_STEPS; t++) {
        // issue canonical xs read for swizzle duty (step t+2), DRAM, early
        float xval = 0.0f;
        if (t + 2 < T_STEPS)
            xval = __ldcg(xs + (size_t)(t + 2) * BH + (size_t)(r0 + er) * H_SZ + j0 + ec);

        // phase 1 guard: xs-swz[t] valid once producers passed step t-1
        if (t >= 2) {
            for (;;) {
                int ok = (lane < 2) ? ((int)(ldflag(pflag) - base) >= t - 1) : 1;
                if (__all_sync(0xffffffffu, ok)) break;
                __nanosleep(16);
            }
            if (lane < 2) (void)ldacq(pflag);
        }

        // xproj MMAs: A from xs ring (L2), B = Wih fragments from smem
        float acc[4][4] = {{0,0,0,0},{0,0,0,0},{0,0,0,0},{0,0,0,0}};
        {
            const uint4* ap = reinterpret_cast<const uint4*>(
                g_xswz[t & (RING - 1)] + rbbase + (c * 8) * 128) + lane;
            uint4 av = __ldcg(ap);
#pragma unroll
            for (int kk = 0; kk < 8; kk++) {
                uint4 nx;
                if (kk < 7) nx = __ldcg(ap + (kk + 1) * 32);
                const int krow = c * KCH + kk * 8 + tg;
#pragma unroll
                for (int nt = 0; nt < 4; nt++) {
                    unsigned wf[2];
                    wf[0] = __float_as_uint(WihS[krow * WST + nt * 8 + g]);
                    wf[1] = __float_as_uint(WihS[(krow + 4) * WST + nt * 8 + g]);
                    mma_tf32(acc[nt], av, wf);
                }
                av = nx;
            }
        }

        // swizzle duty: publish xs[t+2] share into ring (visible via flag t+1)
        if (t + 2 < T_STEPS)
            __stcg(&g_xswz[(t + 2) & (RING - 1)][rbbase + myswz],
                   wmma::__float_to_tf32(xval));

        // phase 2 guard: h[t-1] ready
        if (t > 0) {
            for (;;) {
                int ok = (lane < 2) ? ((int)(ldflag(pflag) - base) >= t) : 1;
                if (__all_sync(0xffffffffu, ok)) break;
                __nanosleep(16);
            }
            if (lane < 2) (void)ldacq(pflag);
        }

        // recurrent MMAs: A from h ping-pong (L2), B = Whh registers
        {
            const uint4* ap = reinterpret_cast<const uint4*>(
                g_hswz[(t + 1) & 1] + rbbase + (c * 8) * 128) + lane;
            uint4 av = __ldcg(ap);
#pragma unroll
            for (int kk = 0; kk < 8; kk++) {
                uint4 nx;
                if (kk < 7) nx = __ldcg(ap + (kk + 1) * 32);
#pragma unroll
                for (int nt = 0; nt < 4; nt++)
                    mma_tf32(acc[nt], av, Bf[kk][nt]);
                av = nx;
            }
        }

        // stage partials
        float* stg = stage + w * (RSZ * SST);
#pragma unroll
        for (int nt = 0; nt < 4; nt++) {
            *reinterpret_cast<float2*>(stg + g * SST + nt * 8 + 2 * tg) =
                make_float2(acc[nt][0], acc[nt][1]);
            *reinterpret_cast<float2*>(stg + (g + 8) * SST + nt * 8 + 2 * tg) =
                make_float2(acc[nt][2], acc[nt][3]);
        }
        __syncthreads();

        // epilogue: reduce 16 partials (xproj + recurrent fused), tanh
        float v = bsum;
#pragma unroll
        for (int k = 0; k < NWARP; k++)
            v += stage[k * (RSZ * SST) + er * SST + ec];
        v = wmma::__float_to_tf32(tanhf(v));

        size_t ooff = (size_t)t * BH + (size_t)(r0 + er) * H_SZ + j0 + ec;
        __stcg(outs + ooff, v);
        __stcg(&g_hswz[t & 1][rbbase + myswz], v);
        if (carry != nullptr && t == T_STEPS - 1)
            __stcg(carry + (size_t)(r0 + er) * H_SZ + j0 + ec, v);
        __syncthreads();

        if (tid == 0) relexch(myflag, base + (unsigned)(t + 1));
    }
}

// ---------------------------------------------------------------------------
extern "C" void kernel_launch(void* const* d_in, const int* in_sizes, int n_in,
                              void* d_out, int out_size) {
    const float* init = (const float*)d_in[0];
    const float* xs   = (const float*)d_in[1];
    const float* Wih  = (const float*)d_in[2];
    const float* bih  = (const float*)d_in[3];
    const float* Whh  = (const float*)d_in[4];
    const float* bhh  = (const float*)d_in[5];

    float* out   = (float*)d_out;
    float* carry = nullptr;
    float* outs;
    if (out_size == BH + TBH) { carry = out; outs = out + BH; }
    else                      { outs = out; }

    int smem = (H_SZ * WST + NWARP * RSZ * SST) * (int)sizeof(float);  // 184320B
    cudaFuncSetAttribute(rnn_fused, cudaFuncAttributeMaxDynamicSharedMemorySize, smem);
    rnn_fused<<<NBLK, 512, smem>>>(init, xs, Wih, bih, Whh, bhh, outs, carry);
}

// round 11
// speedup vs baseline: 1.5118x; 1.0728x over previous
#include <cuda_runtime.h>
#include <mma.h>
#include <cstdint>

using namespace nvcuda;

#define T_STEPS 1024
#define B_SZ    64
#define H_SZ    1024
#define BH      (B_SZ * H_SZ)          /* 65536 */
#define TBH     (T_STEPS * BH)

// ---------------- config ----------------
#define RSZ   16         // batch rows per block
#define CSZ   32         // output cols per block
#define NBLK  128        // 4 row-groups x 32 col-blocks
#define KCH   64         // k columns per warp chunk
#define NWARP 16
#define SST   36         // stage row stride (floats)
#define FPAD  32         // one flag per 128B L2 line
#define RING  4          // xs-swizzle ring depth

__device__ unsigned g_flags[NBLK * FPAD];
__device__ __align__(16) float g_hswz[2][BH];        // fragment-major h ping-pong
__device__ __align__(16) float g_xswz[RING][BH];     // fragment-major xs ring (1MB)

// ---------------- asm helpers ----------------
__device__ __forceinline__ unsigned ldacq(const unsigned* p) {
    unsigned v;
    asm volatile("ld.acquire.gpu.global.u32 %0, [%1];" : "=r"(v) : "l"(p));
    return v;
}
__device__ __forceinline__ unsigned ldflag(const unsigned* p) {
    unsigned v;
    asm volatile("ld.global.cg.u32 %0, [%1];" : "=r"(v) : "l"(p));
    return v;
}
__device__ __forceinline__ void relexch(unsigned* p, unsigned v) {
    unsigned old;
    asm volatile("atom.release.gpu.global.exch.b32 %0, [%1], %2;"
                 : "=r"(old) : "l"(p), "r"(v) : "memory");
}
__device__ __forceinline__ void mma_tf32(float acc[4], const uint4& a, const uint2& b) {
    asm volatile("mma.sync.aligned.m16n8k8.row.col.f32.tf32.tf32.f32 "
                 "{%0,%1,%2,%3}, {%4,%5,%6,%7}, {%8,%9}, {%0,%1,%2,%3};"
                 : "+f"(acc[0]), "+f"(acc[1]), "+f"(acc[2]), "+f"(acc[3])
                 : "r"(a.x), "r"(a.y), "r"(a.z), "r"(a.w), "r"(b.x), "r"(b.y));
}

// fragment-major offset (within one rb slice) for element (r16, gc)
__device__ __forceinline__ int swz_rel(int r16, int gc) {
    int reg  = ((r16 >= 8) ? 1 : 0) | ((gc & 4) ? 2 : 0);
    int lane = 4 * (r16 & 7) + (gc & 3);
    return (((gc >> 6) * 8 + ((gc >> 3) & 7)) * 32 + lane) * 4 + reg;
}

// ---------------------------------------------------------------------------
// Fused persistent kernel: xproj GEMM + RNN scan in one.
// Wih lives in SMEM in FRAGMENT-MAJOR layout: per (chunk,kk,nt) a 32xuint2
// block, so each lane fetches its 2 B-regs with ONE conflict-free LDS.64.
// Whh fragments live in registers (64). Everything else as round-10.
// ---------------------------------------------------------------------------
__global__ void __launch_bounds__(512) rnn_fused(const float* __restrict__ init,
                                                 const float* __restrict__ xs,
                                                 const float* __restrict__ Wih,
                                                 const float* __restrict__ bih,
                                                 const float* __restrict__ Whh,
                                                 const float* __restrict__ bhh,
                                                 float* __restrict__ outs,
                                                 float* __restrict__ carry) {
    extern __shared__ float sm[];
    uint2* WihF  = reinterpret_cast<uint2*>(sm);     // 16*8*4*32 uint2 = 131072 B
    float* stage = sm + 2 * (NWARP * 8 * 4 * 32);    // 16*16*36 f = 36864 B

    const int tid = threadIdx.x, bid = blockIdx.x;
    const int rb = bid & 3, jb = bid >> 2;
    const int r0 = rb * RSZ, j0 = jb * CSZ;
    const int w = tid >> 5, lane = tid & 31;
    const int g = lane >> 2, tg = lane & 3;
    const int c = (w + jb) & 15;             // staggered chunk
    const int er = w, ec = lane;             // this thread's output element

    unsigned* myflag = &g_flags[bid * FPAD];
    const unsigned base = ldflag(myflag);
    const float bsum = bih[j0 + ec] + bhh[j0 + ec];

    const int myswz = swz_rel(er, j0 + ec);
    const int rbbase = rb * 16384;

    // producer flags for chunk c: blocks (rb, 2c) and (rb, 2c+1)
    const unsigned* pflag =
        &g_flags[((((unsigned)(2 * c + (lane & 1))) << 2) | (unsigned)rb) * FPAD];

    // ---- prologue: Wih fragments -> smem, fragment-major (warp w fills chunk c)
#pragma unroll
    for (int kk = 0; kk < 8; kk++)
#pragma unroll
        for (int nt = 0; nt < 4; nt++) {
            int krow = c * KCH + kk * 8 + tg;
            int ncol = j0 + nt * 8 + g;
            uint2 v;
            v.x = __float_as_uint(wmma::__float_to_tf32(Wih[(size_t)krow * H_SZ + ncol]));
            v.y = __float_as_uint(wmma::__float_to_tf32(Wih[(size_t)(krow + 4) * H_SZ + ncol]));
            WihF[((c * 8 + kk) * 4 + nt) * 32 + lane] = v;
        }

    // ---- prologue: Whh fragments -> registers (64 regs) ----
    uint2 Bf[8][4];
#pragma unroll
    for (int kk = 0; kk < 8; kk++)
#pragma unroll
        for (int nt = 0; nt < 4; nt++) {
            int krow = c * KCH + kk * 8 + tg;
            int ncol = j0 + nt * 8 + g;
            Bf[kk][nt].x = __float_as_uint(
                wmma::__float_to_tf32(Whh[(size_t)krow * H_SZ + ncol]));
            Bf[kk][nt].y = __float_as_uint(
                wmma::__float_to_tf32(Whh[(size_t)(krow + 4) * H_SZ + ncol]));
        }

    // ---- prologue: duplicate-swizzle init -> hswz[1], xs[0]->ring0, xs[1]->ring1
#pragma unroll 4
    for (int i = 0; i < 32; i++) {
        int idx = tid + i * 512;             // 0..16383
        int r16 = idx >> 10, gc = idx & 1023;
        int off = rbbase + swz_rel(r16, gc);
        size_t src = (size_t)(r0 + r16) * H_SZ + gc;
        g_hswz[1][off]  = wmma::__float_to_tf32(init[src]);
        g_xswz[0][off]  = wmma::__float_to_tf32(__ldcg(xs + src));
        g_xswz[1][off]  = wmma::__float_to_tf32(__ldcg(xs + BH + src));
    }
    __syncthreads();

#pragma unroll 1
    for (int t = 0; t < T_STEPS; t++) {
        // canonical xs read for swizzle duty (step t+2), DRAM, issued early
        float xval = 0.0f;
        if (t + 2 < T_STEPS)
            xval = __ldcg(xs + (size_t)(t + 2) * BH + (size_t)(r0 + er) * H_SZ + j0 + ec);

        // phase 1 guard: xs-swz[t] valid once producers passed step t-1
        if (t >= 2) {
            for (;;) {
                int ok = (lane < 2) ? ((int)(ldflag(pflag) - base) >= t - 1) : 1;
                if (__all_sync(0xffffffffu, ok)) break;
                __nanosleep(16);
            }
            if (lane < 2) (void)ldacq(pflag);
        }

        // xproj MMAs: A from xs ring (L2), B = Wih fragments via LDS.64
        float acc[4][4] = {{0,0,0,0},{0,0,0,0},{0,0,0,0},{0,0,0,0}};
        {
            const uint4* ap = reinterpret_cast<const uint4*>(
                g_xswz[t & (RING - 1)] + rbbase + (c * 8) * 128) + lane;
            const uint2* wp = WihF + (c * 8) * 4 * 32 + lane;
            uint4 av = __ldcg(ap);
#pragma unroll
            for (int kk = 0; kk < 8; kk++) {
                uint4 nx;
                if (kk < 7) nx = __ldcg(ap + (kk + 1) * 32);
#pragma unroll
                for (int nt = 0; nt < 4; nt++)
                    mma_tf32(acc[nt], av, wp[(kk * 4 + nt) * 32]);
                av = nx;
            }
        }

        // swizzle duty: publish xs[t+2] share into ring
        if (t + 2 < T_STEPS)
            __stcg(&g_xswz[(t + 2) & (RING - 1)][rbbase + myswz],
                   wmma::__float_to_tf32(xval));

        // phase 2 guard: h[t-1] ready
        if (t > 0) {
            for (;;) {
                int ok = (lane < 2) ? ((int)(ldflag(pflag) - base) >= t) : 1;
                if (__all_sync(0xffffffffu, ok)) break;
                __nanosleep(16);
            }
            if (lane < 2) (void)ldacq(pflag);
        }

        // recurrent MMAs: A from h ping-pong (L2), B = Whh registers
        {
            const uint4* ap = reinterpret_cast<const uint4*>(
                g_hswz[(t + 1) & 1] + rbbase + (c * 8) * 128) + lane;
            uint4 av = __ldcg(ap);
#pragma unroll
            for (int kk = 0; kk < 8; kk++) {
                uint4 nx;
                if (kk < 7) nx = __ldcg(ap + (kk + 1) * 32);
#pragma unroll
                for (int nt = 0; nt < 4; nt++)
                    mma_tf32(acc[nt], av, Bf[kk][nt]);
                av = nx;
            }
        }

        // stage partials
        float* stg = stage + w * (RSZ * SST);
#pragma unroll
        for (int nt = 0; nt < 4; nt++) {
            *reinterpret_cast<float2*>(stg + g * SST + nt * 8 + 2 * tg) =
                make_float2(acc[nt][0], acc[nt][1]);
            *reinterpret_cast<float2*>(stg + (g + 8) * SST + nt * 8 + 2 * tg) =
                make_float2(acc[nt][2], acc[nt][3]);
        }
        __syncthreads();

        // epilogue: reduce 16 partials (xproj + recurrent fused), tanh
        float v = bsum;
#pragma unroll
        for (int k = 0; k < NWARP; k++)
            v += stage[k * (RSZ * SST) + er * SST + ec];
        v = wmma::__float_to_tf32(tanhf(v));

        size_t ooff = (size_t)t * BH + (size_t)(r0 + er) * H_SZ + j0 + ec;
        __stcg(outs + ooff, v);
        __stcg(&g_hswz[t & 1][rbbase + myswz], v);
        if (carry != nullptr && t == T_STEPS - 1)
            __stcg(carry + (size_t)(r0 + er) * H_SZ + j0 + ec, v);
        __syncthreads();

        if (tid == 0) relexch(myflag, base + (unsigned)(t + 1));
    }
}

// ---------------------------------------------------------------------------
extern "C" void kernel_launch(void* const* d_in, const int* in_sizes, int n_in,
                              void* d_out, int out_size) {
    const float* init = (const float*)d_in[0];
    const float* xs   = (const float*)d_in[1];
    const float* Wih  = (const float*)d_in[2];
    const float* bih  = (const float*)d_in[3];
    const float* Whh  = (const float*)d_in[4];
    const float* bhh  = (const float*)d_in[5];

    float* out   = (float*)d_out;
    float* carry = nullptr;
    float* outs;
    if (out_size == BH + TBH) { carry = out; outs = out + BH; }
    else                      { outs = out; }

    int smem = (NWARP * 8 * 4 * 32 * 2 + NWARP * RSZ * SST) * (int)sizeof(float); // 167936B
    cudaFuncSetAttribute(rnn_fused, cudaFuncAttributeMaxDynamicSharedMemorySize, smem);
    rnn_fused<<<NBLK, 512, smem>>>(init, xs, Wih, bih, Whh, bhh, outs, carry);
}

// round 12
// speedup vs baseline: 1.7575x; 1.1625x over previous
#include <cuda_runtime.h>
#include <mma.h>
#include <cstdint>

using namespace nvcuda;

#define T_STEPS 1024
#define B_SZ    64
#define H_SZ    1024
#define BH      (B_SZ * H_SZ)          /* 65536 */
#define TBH     (T_STEPS * BH)

// ---------------- config ----------------
#define RSZ   16         // batch rows per block
#define CSZ   32         // output cols per block
#define NBLK  128        // 4 row-groups x 32 col-blocks
#define KCH   64         // k columns per warp chunk
#define NWARP 16
#define SST   36         // stage row stride (floats)
#define FPAD  32         // one flag per 128B L2 line
#define RING  4          // xs-swizzle ring depth

__device__ unsigned g_flags[NBLK * FPAD];
__device__ __align__(16) float g_hswz[2][BH];        // fragment-major h ping-pong
__device__ __align__(16) float g_xswz[RING][BH];     // fragment-major xs ring (1MB)

// ---------------- asm helpers ----------------
__device__ __forceinline__ unsigned ldacq(const unsigned* p) {
    unsigned v;
    asm volatile("ld.acquire.gpu.global.u32 %0, [%1];" : "=r"(v) : "l"(p));
    return v;
}
__device__ __forceinline__ unsigned ldflag(const unsigned* p) {
    unsigned v;
    asm volatile("ld.global.cg.u32 %0, [%1];" : "=r"(v) : "l"(p));
    return v;
}
__device__ __forceinline__ void relexch(unsigned* p, unsigned v) {
    unsigned old;
    asm volatile("atom.release.gpu.global.exch.b32 %0, [%1], %2;"
                 : "=r"(old) : "l"(p), "r"(v) : "memory");
}
__device__ __forceinline__ void mma_tf32(float acc[4], const uint4& a, const uint2& b) {
    asm volatile("mma.sync.aligned.m16n8k8.row.col.f32.tf32.tf32.f32 "
                 "{%0,%1,%2,%3}, {%4,%5,%6,%7}, {%8,%9}, {%0,%1,%2,%3};"
                 : "+f"(acc[0]), "+f"(acc[1]), "+f"(acc[2]), "+f"(acc[3])
                 : "r"(a.x), "r"(a.y), "r"(a.z), "r"(a.w), "r"(b.x), "r"(b.y));
}

// fragment-major offset (within one rb slice) for element (r16, gc)
__device__ __forceinline__ int swz_rel(int r16, int gc) {
    int reg  = ((r16 >= 8) ? 1 : 0) | ((gc & 4) ? 2 : 0);
    int lane = 4 * (r16 & 7) + (gc & 3);
    return (((gc >> 6) * 8 + ((gc >> 3) & 7)) * 32 + lane) * 4 + reg;
}

// ---------------------------------------------------------------------------
// Fused persistent kernel: xproj GEMM + RNN scan.
// Round-12 deltas vs round-11:
//  - xs-poll DELETED (guard provably established by h-poll at step t-1)
//  - h-poll carries acquire semantics directly (no separate ldacq)
//  - canonical outs/carry store moved after the flag release
// ---------------------------------------------------------------------------
__global__ void __launch_bounds__(512) rnn_fused(const float* __restrict__ init,
                                                 const float* __restrict__ xs,
                                                 const float* __restrict__ Wih,
                                                 const float* __restrict__ bih,
                                                 const float* __restrict__ Whh,
                                                 const float* __restrict__ bhh,
                                                 float* __restrict__ outs,
                                                 float* __restrict__ carry) {
    extern __shared__ float sm[];
    uint2* WihF  = reinterpret_cast<uint2*>(sm);     // 16*8*4*32 uint2 = 131072 B
    float* stage = sm + 2 * (NWARP * 8 * 4 * 32);    // 16*16*36 f = 36864 B

    const int tid = threadIdx.x, bid = blockIdx.x;
    const int rb = bid & 3, jb = bid >> 2;
    const int r0 = rb * RSZ, j0 = jb * CSZ;
    const int w = tid >> 5, lane = tid & 31;
    const int g = lane >> 2, tg = lane & 3;
    const int c = (w + jb) & 15;             // staggered chunk
    const int er = w, ec = lane;             // this thread's output element

    unsigned* myflag = &g_flags[bid * FPAD];
    const unsigned base = ldflag(myflag);
    const float bsum = bih[j0 + ec] + bhh[j0 + ec];

    const int myswz = swz_rel(er, j0 + ec);
    const int rbbase = rb * 16384;

    // producer flags for chunk c: blocks (rb, 2c) and (rb, 2c+1)
    const unsigned* pflag =
        &g_flags[((((unsigned)(2 * c + (lane & 1))) << 2) | (unsigned)rb) * FPAD];

    // ---- prologue: Wih fragments -> smem, fragment-major (warp w fills chunk c)
#pragma unroll
    for (int kk = 0; kk < 8; kk++)
#pragma unroll
        for (int nt = 0; nt < 4; nt++) {
            int krow = c * KCH + kk * 8 + tg;
            int ncol = j0 + nt * 8 + g;
            uint2 v;
            v.x = __float_as_uint(wmma::__float_to_tf32(Wih[(size_t)krow * H_SZ + ncol]));
            v.y = __float_as_uint(wmma::__float_to_tf32(Wih[(size_t)(krow + 4) * H_SZ + ncol]));
            WihF[((c * 8 + kk) * 4 + nt) * 32 + lane] = v;
        }

    // ---- prologue: Whh fragments -> registers (64 regs) ----
    uint2 Bf[8][4];
#pragma unroll
    for (int kk = 0; kk < 8; kk++)
#pragma unroll
        for (int nt = 0; nt < 4; nt++) {
            int krow = c * KCH + kk * 8 + tg;
            int ncol = j0 + nt * 8 + g;
            Bf[kk][nt].x = __float_as_uint(
                wmma::__float_to_tf32(Whh[(size_t)krow * H_SZ + ncol]));
            Bf[kk][nt].y = __float_as_uint(
                wmma::__float_to_tf32(Whh[(size_t)(krow + 4) * H_SZ + ncol]));
        }

    // ---- prologue: duplicate-swizzle init -> hswz[1], xs[0]->ring0, xs[1]->ring1
#pragma unroll 4
    for (int i = 0; i < 32; i++) {
        int idx = tid + i * 512;             // 0..16383
        int r16 = idx >> 10, gc = idx & 1023;
        int off = rbbase + swz_rel(r16, gc);
        size_t src = (size_t)(r0 + r16) * H_SZ + gc;
        g_hswz[1][off]  = wmma::__float_to_tf32(init[src]);
        g_xswz[0][off]  = wmma::__float_to_tf32(__ldcg(xs + src));
        g_xswz[1][off]  = wmma::__float_to_tf32(__ldcg(xs + BH + src));
    }
    __syncthreads();

#pragma unroll 1
    for (int t = 0; t < T_STEPS; t++) {
        // canonical xs read for swizzle duty (step t+2), DRAM, issued early
        float xval = 0.0f;
        if (t + 2 < T_STEPS)
            xval = __ldcg(xs + (size_t)(t + 2) * BH + (size_t)(r0 + er) * H_SZ + j0 + ec);

        // xproj MMAs immediately — xs ring slot t guarded by h-poll at step t-1
        float acc[4][4] = {{0,0,0,0},{0,0,0,0},{0,0,0,0},{0,0,0,0}};
        {
            const uint4* ap = reinterpret_cast<const uint4*>(
                g_xswz[t & (RING - 1)] + rbbase + (c * 8) * 128) + lane;
            const uint2* wp = WihF + (c * 8) * 4 * 32 + lane;
            uint4 av = __ldcg(ap);
#pragma unroll
            for (int kk = 0; kk < 8; kk++) {
                uint4 nx;
                if (kk < 7) nx = __ldcg(ap + (kk + 1) * 32);
#pragma unroll
                for (int nt = 0; nt < 4; nt++)
                    mma_tf32(acc[nt], av, wp[(kk * 4 + nt) * 32]);
                av = nx;
            }
        }

        // swizzle duty: publish xs[t+2] share into ring
        if (t + 2 < T_STEPS)
            __stcg(&g_xswz[(t + 2) & (RING - 1)][rbbase + myswz],
                   wmma::__float_to_tf32(xval));

        // h guard: acquire-poll (single trip per detection)
        if (t > 0) {
            for (;;) {
                int ok = (lane < 2) ? ((int)(ldacq(pflag) - base) >= t) : 1;
                if (__all_sync(0xffffffffu, ok)) break;
                __nanosleep(16);
            }
        }

        // recurrent MMAs: A from h ping-pong (L2), B = Whh registers
        {
            const uint4* ap = reinterpret_cast<const uint4*>(
                g_hswz[(t + 1) & 1] + rbbase + (c * 8) * 128) + lane;
            uint4 av = __ldcg(ap);
#pragma unroll
            for (int kk = 0; kk < 8; kk++) {
                uint4 nx;
                if (kk < 7) nx = __ldcg(ap + (kk + 1) * 32);
#pragma unroll
                for (int nt = 0; nt < 4; nt++)
                    mma_tf32(acc[nt], av, Bf[kk][nt]);
                av = nx;
            }
        }

        // stage partials
        float* stg = stage + w * (RSZ * SST);
#pragma unroll
        for (int nt = 0; nt < 4; nt++) {
            *reinterpret_cast<float2*>(stg + g * SST + nt * 8 + 2 * tg) =
                make_float2(acc[nt][0], acc[nt][1]);
            *reinterpret_cast<float2*>(stg + (g + 8) * SST + nt * 8 + 2 * tg) =
                make_float2(acc[nt][2], acc[nt][3]);
        }
        __syncthreads();

        // epilogue: reduce 16 partials (xproj + recurrent fused), tanh
        float v = bsum;
#pragma unroll
        for (int k = 0; k < NWARP; k++)
            v += stage[k * (RSZ * SST) + er * SST + ec];
        v = wmma::__float_to_tf32(tanhf(v));

        // publish h (L2 ping-pong) FIRST, then barrier + release; DRAM after
        __stcg(&g_hswz[t & 1][rbbase + myswz], v);
        __syncthreads();
        if (tid == 0) relexch(myflag, base + (unsigned)(t + 1));

        size_t ooff = (size_t)t * BH + (size_t)(r0 + er) * H_SZ + j0 + ec;
        __stcg(outs + ooff, v);
        if (carry != nullptr && t == T_STEPS - 1)
            __stcg(carry + (size_t)(r0 + er) * H_SZ + j0 + ec, v);
    }
}

// ---------------------------------------------------------------------------
extern "C" void kernel_launch(void* const* d_in, const int* in_sizes, int n_in,
                              void* d_out, int out_size) {
    const float* init = (const float*)d_in[0];
    const float* xs   = (const float*)d_in[1];
    const float* Wih  = (const float*)d_in[2];
    const float* bih  = (const float*)d_in[3];
    const float* Whh  = (const float*)d_in[4];
    const float* bhh  = (const float*)d_in[5];

    float* out   = (float*)d_out;
    float* carry = nullptr;
    float* outs;
    if (out_size == BH + TBH) { carry = out; outs = out + BH; }
    else                      { outs = out; }

    int smem = (NWARP * 8 * 4 * 32 * 2 + NWARP * RSZ * SST) * (int)sizeof(float); // 167936B
    cudaFuncSetAttribute(rnn_fused, cudaFuncAttributeMaxDynamicSharedMemorySize, smem);
    rnn_fused<<<NBLK, 512, smem>>>(init, xs, Wih, bih, Whh, bhh, outs, carry);
}